// round 1
// baseline (speedup 1.0000x reference)
#include <cuda_runtime.h>
#include <math.h>

// Problem constants
#define BATCH 8
#define NPOS 1024            // 32x32
#define DIM 128
#define HEADS 8
#define GRID 32              // H = W = 32
#define POSITIONS (BATCH*NPOS)   // 8192

// ---------------- scratch (static device memory; no allocs allowed) -------
__device__ float g_xn[POSITIONS*DIM];            // layernormed x           4MB
__device__ float g_S[POSITIONS*DIM];             // 2D inclusive cumsum     4MB
__device__ float g_regions[POSITIONS*4*DIM];     // 4 region means         16MB
__device__ float g_Wf[HEADS*DIM*DIM];            // Wqkv_h @ Wq
__device__ float g_T[HEADS*DIM*DIM];             // Wo @ Wout_h
__device__ float g_M[DIM*HEADS*DIM];             // Mcat [128][1024]
__device__ float g_W3[HEADS*DIM*DIM];            // W3cat [1024][128]
__device__ float g_bf[HEADS*DIM];
__device__ float g_bu[HEADS*DIM];                // bias for U columns
__device__ float g_bfinal[DIM];
__device__ float g_U[POSITIONS*HEADS*DIM];       // 33.5MB
__device__ float g_C[POSITIONS*HEADS*DIM];       // 33.5MB
__device__ float g_Yp[HEADS*POSITIONS*DIM];      // per-head partials 33.5MB

// ---------------- 128x128x128 matmul helper (256 threads) -----------------
__device__ __forceinline__ void mm128(const float* __restrict__ A, int lda,
                                      const float* __restrict__ B, int ldb, int transB,
                                      float* __restrict__ Cdst, int ldc)
{
    const int tid = threadIdx.x;
    const int tx = tid & 15, ty = tid >> 4;
    __shared__ float As[16][128];
    __shared__ float Bs[16][128];
    float acc[8][8];
#pragma unroll
    for (int i = 0; i < 8; i++)
#pragma unroll
        for (int j = 0; j < 8; j++) acc[i][j] = 0.f;

    for (int k0 = 0; k0 < 128; k0 += 16) {
        for (int t = tid; t < 2048; t += 256) {
            int m = t >> 4, kk = t & 15;
            As[kk][m] = A[m*lda + k0 + kk];
        }
        for (int t = tid; t < 2048; t += 256) {
            int kk = t >> 7, n = t & 127;
            Bs[kk][n] = transB ? B[n*ldb + k0 + kk] : B[(k0+kk)*ldb + n];
        }
        __syncthreads();
#pragma unroll
        for (int kk = 0; kk < 16; kk++) {
            float a[8], b[8];
#pragma unroll
            for (int i = 0; i < 8; i++) a[i] = As[kk][ty*8 + i];
#pragma unroll
            for (int j = 0; j < 8; j++) b[j] = Bs[kk][tx*8 + j];
#pragma unroll
            for (int i = 0; i < 8; i++)
#pragma unroll
                for (int j = 0; j < 8; j++) acc[i][j] += a[i]*b[j];
        }
        __syncthreads();
    }
#pragma unroll
    for (int i = 0; i < 8; i++)
#pragma unroll
        for (int j = 0; j < 8; j++)
            Cdst[(ty*8 + i)*ldc + tx*8 + j] = acc[i][j];
}

// ---------------- weight precompute, stage A -------------------------------
// blocks 0-7 : Wf_h = Wqkv[:, h*128:(h+1)*128] @ Wq ;  bf_h = bqkv_h @ Wq
// blocks 8-15: T_h  = Wo @ Wout[h*128:(h+1)*128, :]
__global__ void precompA_kernel(const float* __restrict__ Wqkv, const float* __restrict__ bqkv,
                                const float* __restrict__ Wq, const float* __restrict__ Wo,
                                const float* __restrict__ Wout)
{
    int blk = blockIdx.x;
    if (blk < 8) {
        int h = blk;
        mm128(Wqkv + h*128, 3*HEADS*DIM, Wq, DIM, 0, g_Wf + h*DIM*DIM, DIM);
        for (int e = threadIdx.x; e < DIM; e += 256) {
            float s = 0.f;
            for (int c = 0; c < DIM; c++) s += bqkv[h*DIM + c] * Wq[c*DIM + e];
            g_bf[h*DIM + e] = s;
        }
    } else {
        int h = blk - 8;
        mm128(Wo, DIM, Wout + h*DIM*DIM, DIM, 0, g_T + h*DIM*DIM, DIM);
    }
}

// ---------------- weight precompute, stage B -------------------------------
// blocks 0-7 : M_h  = Wf_h @ Wk^T  -> Mcat[d][h*128+d2];  bu_h = bf_h @ Wk^T
// blocks 8-15: W3_h = Wv @ T_h     -> W3cat[h*128+d][e];  block 8 also bfinal
__global__ void precompB_kernel(const float* __restrict__ Wk, const float* __restrict__ Wv,
                                const float* __restrict__ Wout, const float* __restrict__ bo,
                                const float* __restrict__ bout)
{
    int blk = blockIdx.x;
    if (blk < 8) {
        int h = blk;
        mm128(g_Wf + h*DIM*DIM, DIM, Wk, DIM, 1, g_M + h*DIM, HEADS*DIM);
        for (int d2 = threadIdx.x; d2 < DIM; d2 += 256) {
            float s = 0.f;
            for (int e = 0; e < DIM; e++) s += g_bf[h*DIM + e] * Wk[d2*DIM + e];
            g_bu[h*DIM + d2] = s;
        }
    } else {
        int h = blk - 8;
        mm128(Wv, DIM, g_T + h*DIM*DIM, DIM, 0, g_W3 + h*DIM*DIM, DIM);
        if (h == 0) {
            for (int e = threadIdx.x; e < DIM; e += 256) {
                float s = bout[e];
                for (int c = 0; c < HEADS*DIM; c++) s += bo[c & 127] * Wout[c*DIM + e];
                g_bfinal[e] = s;
            }
        }
    }
}

// ---------------- layernorm ------------------------------------------------
__global__ void ln_kernel(const float* __restrict__ x, const float* __restrict__ g,
                          const float* __restrict__ b)
{
    int row = blockIdx.x;
    int d = threadIdx.x;
    float v = x[row*DIM + d];
    float s = v, s2 = v*v;
#pragma unroll
    for (int o = 16; o > 0; o >>= 1) {
        s  += __shfl_xor_sync(0xffffffffu, s, o);
        s2 += __shfl_xor_sync(0xffffffffu, s2, o);
    }
    __shared__ float ws[4], ws2[4];
    if ((d & 31) == 0) { ws[d >> 5] = s; ws2[d >> 5] = s2; }
    __syncthreads();
    float S  = ws[0] + ws[1] + ws[2] + ws[3];
    float S2 = ws2[0] + ws2[1] + ws2[2] + ws2[3];
    float mu = S * (1.f/128.f);
    float var = S2 * (1.f/128.f) - mu*mu;
    float inv = rsqrtf(var + 1e-5f);
    g_xn[row*DIM + d] = (v - mu) * inv * g[d] + b[d];
}

// ---------------- integral image: row cumsum then column cumsum ------------
__global__ void rowcum_kernel()
{
    int bh = blockIdx.x;        // b*32 + h
    int d = threadIdx.x;
    float run = 0.f;
    for (int w = 0; w < GRID; w++) {
        int idx = (bh*GRID + w)*DIM + d;
        run += g_xn[idx];
        g_S[idx] = run;
    }
}

__global__ void colcum_kernel()
{
    int b = blockIdx.x >> 5, w = blockIdx.x & 31;
    int d = threadIdx.x;
    float run = 0.f;
    for (int h = 0; h < GRID; h++) {
        int idx = ((b*GRID + h)*GRID + w)*DIM + d;
        run += g_S[idx];
        g_S[idx] = run;
    }
}

// ---------------- region means ---------------------------------------------
__global__ void regions_kernel()
{
    int pos = blockIdx.x;                 // b*1024 + h*32 + w
    int b = pos >> 10;
    int hw = pos & 1023;
    int h = hw >> 5, w = hw & 31;
    int d = threadIdx.x;
    const float* Sb = g_S + b*GRID*GRID*DIM;
#define SS(hh,ww) (((hh) < 0 || (ww) < 0) ? 0.f : Sb[((hh)*GRID + (ww))*DIM + d])
    float s_hw  = SS(h, w);
    float s_hW  = SS(h, GRID-1);
    float s_Hw  = SS(GRID-1, w);
    float s_HW  = SS(GRID-1, GRID-1);
    float s_h1w1 = SS(h-1, w-1);
    float s_h1w  = SS(h-1, w);
    float s_hw1  = SS(h, w-1);
    float s_h1W  = SS(h-1, GRID-1);
    float s_Hw1  = SS(GRID-1, w-1);
#undef SS
    float hp1 = (float)(h+1), wp1 = (float)(w+1);
    float hr = (float)(GRID - h), wr = (float)(GRID - w);
    float* R = g_regions + pos*4*DIM;
    R[0*DIM + d] = s_hw / (hp1*wp1);
    R[1*DIM + d] = (s_hW - s_hw1) / (hp1*wr);
    R[2*DIM + d] = (s_Hw - s_h1w) / (hr*wp1);
    R[3*DIM + d] = (s_HW - s_h1W - s_Hw1 + s_h1w1) / (hr*wr);
}

// ---------------- U = XN @ Mcat + bu   [8192,128]x[128,1024] ---------------
__global__ void gemmU_kernel()
{
    const int tid = threadIdx.x;
    const int tx = tid & 15, ty = tid >> 4;
    const int m0 = blockIdx.x * 128, n0 = blockIdx.y * 128;
    __shared__ float As[16][128];
    __shared__ float Bs[16][128];
    float acc[8][8];
#pragma unroll
    for (int i = 0; i < 8; i++)
#pragma unroll
        for (int j = 0; j < 8; j++) acc[i][j] = 0.f;

    for (int k0 = 0; k0 < 128; k0 += 16) {
        for (int t = tid; t < 2048; t += 256) {
            int m = t >> 4, kk = t & 15;
            As[kk][m] = g_xn[(m0+m)*DIM + k0 + kk];
        }
        for (int t = tid; t < 2048; t += 256) {
            int kk = t >> 7, n = t & 127;
            Bs[kk][n] = g_M[(k0+kk)*(HEADS*DIM) + n0 + n];
        }
        __syncthreads();
#pragma unroll
        for (int kk = 0; kk < 16; kk++) {
            float a[8], b[8];
#pragma unroll
            for (int i = 0; i < 8; i++) a[i] = As[kk][ty*8 + i];
#pragma unroll
            for (int j = 0; j < 8; j++) b[j] = Bs[kk][tx*8 + j];
#pragma unroll
            for (int i = 0; i < 8; i++)
#pragma unroll
                for (int j = 0; j < 8; j++) acc[i][j] += a[i]*b[j];
        }
        __syncthreads();
    }
#pragma unroll
    for (int i = 0; i < 8; i++)
#pragma unroll
        for (int j = 0; j < 8; j++)
            g_U[(m0 + ty*8 + i)*(HEADS*DIM) + n0 + tx*8 + j] =
                acc[i][j] + g_bu[n0 + tx*8 + j];
}

// ---------------- softmax over 4 regions + aggregation ---------------------
__global__ void attn_kernel()
{
    int pos = blockIdx.x;
    int tid = threadIdx.x;
    __shared__ float u[HEADS*DIM];
    __shared__ float reg[4][DIM];
    __shared__ float prob[HEADS][4];

    for (int t = tid; t < HEADS*DIM; t += 256) u[t] = g_U[pos*HEADS*DIM + t];
    for (int t = tid; t < 4*DIM; t += 256) reg[t >> 7][t & 127] = g_regions[pos*4*DIM + t];
    __syncthreads();

    int wid = tid >> 5, lane = tid & 31;   // 8 warps = 8 heads
    float d0 = 0.f, d1 = 0.f, d2 = 0.f, d3 = 0.f;
    const float* uh = u + wid*DIM;
#pragma unroll
    for (int dd = lane; dd < DIM; dd += 32) {
        float uv = uh[dd];
        d0 += uv * reg[0][dd];
        d1 += uv * reg[1][dd];
        d2 += uv * reg[2][dd];
        d3 += uv * reg[3][dd];
    }
#pragma unroll
    for (int o = 16; o > 0; o >>= 1) {
        d0 += __shfl_xor_sync(0xffffffffu, d0, o);
        d1 += __shfl_xor_sync(0xffffffffu, d1, o);
        d2 += __shfl_xor_sync(0xffffffffu, d2, o);
        d3 += __shfl_xor_sync(0xffffffffu, d3, o);
    }
    if (lane == 0) {
        const float scale = 0.25f;   // (dim/heads)^-0.5 = 16^-0.5
        float s0 = d0*scale, s1 = d1*scale, s2 = d2*scale, s3 = d3*scale;
        float m = fmaxf(fmaxf(s0, s1), fmaxf(s2, s3));
        float e0 = expf(s0 - m), e1 = expf(s1 - m), e2 = expf(s2 - m), e3 = expf(s3 - m);
        float inv = 1.f / (e0 + e1 + e2 + e3);
        prob[wid][0] = e0*inv; prob[wid][1] = e1*inv;
        prob[wid][2] = e2*inv; prob[wid][3] = e3*inv;
    }
    __syncthreads();

    for (int t = tid; t < HEADS*DIM; t += 256) {
        int h = t >> 7, dd = t & 127;
        float c = prob[h][0]*reg[0][dd] + prob[h][1]*reg[1][dd]
                + prob[h][2]*reg[2][dd] + prob[h][3]*reg[3][dd];
        g_C[pos*HEADS*DIM + t] = c;
    }
}

// ---------------- Yp[h] = C[:, h*128:(h+1)*128] @ W3_h ---------------------
__global__ void gemmY_kernel()
{
    const int tid = threadIdx.x;
    const int tx = tid & 15, ty = tid >> 4;
    const int m0 = blockIdx.x * 128;
    const int h = blockIdx.z;
    const float* A = g_C + h*DIM;            // lda = 1024
    const float* B = g_W3 + h*DIM*DIM;       // ldb = 128
    float* Cdst = g_Yp + h*POSITIONS*DIM;

    __shared__ float As[16][128];
    __shared__ float Bs[16][128];
    float acc[8][8];
#pragma unroll
    for (int i = 0; i < 8; i++)
#pragma unroll
        for (int j = 0; j < 8; j++) acc[i][j] = 0.f;

    for (int k0 = 0; k0 < 128; k0 += 16) {
        for (int t = tid; t < 2048; t += 256) {
            int m = t >> 4, kk = t & 15;
            As[kk][m] = A[(m0+m)*(HEADS*DIM) + k0 + kk];
        }
        for (int t = tid; t < 2048; t += 256) {
            int kk = t >> 7, n = t & 127;
            Bs[kk][n] = B[(k0+kk)*DIM + n];
        }
        __syncthreads();
#pragma unroll
        for (int kk = 0; kk < 16; kk++) {
            float a[8], b[8];
#pragma unroll
            for (int i = 0; i < 8; i++) a[i] = As[kk][ty*8 + i];
#pragma unroll
            for (int j = 0; j < 8; j++) b[j] = Bs[kk][tx*8 + j];
#pragma unroll
            for (int i = 0; i < 8; i++)
#pragma unroll
                for (int j = 0; j < 8; j++) acc[i][j] += a[i]*b[j];
        }
        __syncthreads();
    }
#pragma unroll
    for (int i = 0; i < 8; i++)
#pragma unroll
        for (int j = 0; j < 8; j++)
            Cdst[(m0 + ty*8 + i)*DIM + tx*8 + j] = acc[i][j];
}

// ---------------- final reduction over heads + bias ------------------------
__global__ void reduceY_kernel(float* __restrict__ out)
{
    int i = blockIdx.x * 256 + threadIdx.x;   // i < 8192*128
    float s = g_bfinal[i & 127];
#pragma unroll
    for (int h = 0; h < HEADS; h++) s += g_Yp[h*POSITIONS*DIM + i];
    out[i] = s;
}

// ---------------- launch ----------------------------------------------------
extern "C" void kernel_launch(void* const* d_in, const int* in_sizes, int n_in,
                              void* d_out, int out_size)
{
    const float* x    = (const float*)d_in[0];
    const float* ln_g = (const float*)d_in[1];
    const float* ln_b = (const float*)d_in[2];
    const float* Wqkv = (const float*)d_in[3];
    const float* bqkv = (const float*)d_in[4];
    const float* Wq   = (const float*)d_in[5];
    const float* Wk   = (const float*)d_in[6];
    const float* Wv   = (const float*)d_in[7];
    const float* Wo   = (const float*)d_in[8];
    const float* bo   = (const float*)d_in[9];
    const float* Wout = (const float*)d_in[10];
    const float* bout = (const float*)d_in[11];
    float* out = (float*)d_out;

    precompA_kernel<<<16, 256>>>(Wqkv, bqkv, Wq, Wo, Wout);
    precompB_kernel<<<16, 256>>>(Wk, Wv, Wout, bo, bout);
    ln_kernel<<<POSITIONS, 128>>>(x, ln_g, ln_b);
    rowcum_kernel<<<BATCH*GRID, 128>>>();
    colcum_kernel<<<BATCH*GRID, 128>>>();
    regions_kernel<<<POSITIONS, 128>>>();
    gemmU_kernel<<<dim3(POSITIONS/128, HEADS, 1), 256>>>();
    attn_kernel<<<POSITIONS, 256>>>();
    gemmY_kernel<<<dim3(POSITIONS/128, 1, HEADS), 256>>>();
    reduceY_kernel<<<POSITIONS*DIM/256, 256>>>(out);
}

// round 2
// speedup vs baseline: 1.5236x; 1.5236x over previous
#include <cuda_runtime.h>
#include <cuda_bf16.h>
#include <math.h>

// Problem constants
#define BATCH 8
#define NPOS 1024            // 32x32
#define DIM 128
#define HEADS 8
#define GRID 32              // H = W = 32
#define POSITIONS (BATCH*NPOS)   // 8192

// ---------------- scratch (static device memory; no allocs allowed) -------
__device__ float g_xn[POSITIONS*DIM];            // layernormed x
__device__ float g_S[POSITIONS*DIM];             // 2D inclusive cumsum
__device__ float g_regions[POSITIONS*4*DIM];     // 4 region means
__device__ float g_Wf[HEADS*DIM*DIM];            // Wqkv_h @ Wq
__device__ float g_T[HEADS*DIM*DIM];             // Wo @ Wout_h
__device__ float g_M[DIM*HEADS*DIM];             // Mcat [128][1024]
__device__ float g_W3[HEADS*DIM*DIM];            // W3cat [1024][128]
__device__ float g_bf[HEADS*DIM];
__device__ float g_bu[HEADS*DIM];
__device__ float g_bfinal[DIM];
__device__ float g_U[POSITIONS*HEADS*DIM];       // attention logits (pre-scale)
__device__ float g_Yp[HEADS*POSITIONS*DIM];      // per-head partials

// bf16 split buffers (x = hi + lo, ~16 effective mantissa bits)
__device__ __nv_bfloat16 g_XNhi[POSITIONS*DIM];
__device__ __nv_bfloat16 g_XNlo[POSITIONS*DIM];
__device__ __nv_bfloat16 g_Mhi[DIM*HEADS*DIM];
__device__ __nv_bfloat16 g_Mlo[DIM*HEADS*DIM];
__device__ __nv_bfloat16 g_W3hi[HEADS*DIM*DIM];
__device__ __nv_bfloat16 g_W3lo[HEADS*DIM*DIM];
__device__ __nv_bfloat16 g_Chi[POSITIONS*HEADS*DIM];
__device__ __nv_bfloat16 g_Clo[POSITIONS*HEADS*DIM];

// ---------------- mma/ldmatrix helpers -------------------------------------
__device__ __forceinline__ unsigned smem_u32(const void* p) {
    return (unsigned)__cvta_generic_to_shared(p);
}
__device__ __forceinline__ void ldmatrix_x4(unsigned* r, unsigned addr) {
    asm volatile("ldmatrix.sync.aligned.m8n8.x4.shared.b16 {%0,%1,%2,%3}, [%4];"
        : "=r"(r[0]), "=r"(r[1]), "=r"(r[2]), "=r"(r[3]) : "r"(addr));
}
__device__ __forceinline__ void ldmatrix_x2t(unsigned* r, unsigned addr) {
    asm volatile("ldmatrix.sync.aligned.m8n8.x2.trans.shared.b16 {%0,%1}, [%2];"
        : "=r"(r[0]), "=r"(r[1]) : "r"(addr));
}
__device__ __forceinline__ void mma_bf16(float* d, const unsigned* a, const unsigned* b) {
    asm volatile("mma.sync.aligned.m16n8k16.row.col.f32.bf16.bf16.f32 "
        "{%0,%1,%2,%3}, {%4,%5,%6,%7}, {%8,%9}, {%0,%1,%2,%3};"
        : "+f"(d[0]), "+f"(d[1]), "+f"(d[2]), "+f"(d[3])
        : "r"(a[0]), "r"(a[1]), "r"(a[2]), "r"(a[3]), "r"(b[0]), "r"(b[1]));
}

// ---------------- 128x128x128 FFMA matmul helper (weight precompute only) --
__device__ __forceinline__ void mm128(const float* __restrict__ A, int lda,
                                      const float* __restrict__ B, int ldb, int transB,
                                      float* __restrict__ Cdst, int ldc)
{
    const int tid = threadIdx.x;
    const int tx = tid & 15, ty = tid >> 4;
    __shared__ float As[16][128];
    __shared__ float Bs[16][128];
    float acc[8][8];
#pragma unroll
    for (int i = 0; i < 8; i++)
#pragma unroll
        for (int j = 0; j < 8; j++) acc[i][j] = 0.f;

    for (int k0 = 0; k0 < 128; k0 += 16) {
        for (int t = tid; t < 2048; t += 256) {
            int m = t >> 4, kk = t & 15;
            As[kk][m] = A[m*lda + k0 + kk];
        }
        for (int t = tid; t < 2048; t += 256) {
            int kk = t >> 7, n = t & 127;
            Bs[kk][n] = transB ? B[n*ldb + k0 + kk] : B[(k0+kk)*ldb + n];
        }
        __syncthreads();
#pragma unroll
        for (int kk = 0; kk < 16; kk++) {
            float a[8], b[8];
#pragma unroll
            for (int i = 0; i < 8; i++) a[i] = As[kk][ty*8 + i];
#pragma unroll
            for (int j = 0; j < 8; j++) b[j] = Bs[kk][tx*8 + j];
#pragma unroll
            for (int i = 0; i < 8; i++)
#pragma unroll
                for (int j = 0; j < 8; j++) acc[i][j] += a[i]*b[j];
        }
        __syncthreads();
    }
#pragma unroll
    for (int i = 0; i < 8; i++)
#pragma unroll
        for (int j = 0; j < 8; j++)
            Cdst[(ty*8 + i)*ldc + tx*8 + j] = acc[i][j];
}

// ---------------- weight precompute, stage A -------------------------------
__global__ void precompA_kernel(const float* __restrict__ Wqkv, const float* __restrict__ bqkv,
                                const float* __restrict__ Wq, const float* __restrict__ Wo,
                                const float* __restrict__ Wout)
{
    int blk = blockIdx.x;
    if (blk < 8) {
        int h = blk;
        mm128(Wqkv + h*128, 3*HEADS*DIM, Wq, DIM, 0, g_Wf + h*DIM*DIM, DIM);
        for (int e = threadIdx.x; e < DIM; e += 256) {
            float s = 0.f;
            for (int c = 0; c < DIM; c++) s += bqkv[h*DIM + c] * Wq[c*DIM + e];
            g_bf[h*DIM + e] = s;
        }
    } else {
        int h = blk - 8;
        mm128(Wo, DIM, Wout + h*DIM*DIM, DIM, 0, g_T + h*DIM*DIM, DIM);
    }
}

// ---------------- weight precompute, stage B -------------------------------
__global__ void precompB_kernel(const float* __restrict__ Wk, const float* __restrict__ Wv,
                                const float* __restrict__ Wout, const float* __restrict__ bo,
                                const float* __restrict__ bout)
{
    int blk = blockIdx.x;
    if (blk < 8) {
        int h = blk;
        mm128(g_Wf + h*DIM*DIM, DIM, Wk, DIM, 1, g_M + h*DIM, HEADS*DIM);
        for (int d2 = threadIdx.x; d2 < DIM; d2 += 256) {
            float s = 0.f;
            for (int e = 0; e < DIM; e++) s += g_bf[h*DIM + e] * Wk[d2*DIM + e];
            g_bu[h*DIM + d2] = s;
        }
    } else {
        int h = blk - 8;
        mm128(Wv, DIM, g_T + h*DIM*DIM, DIM, 0, g_W3 + h*DIM*DIM, DIM);
        if (h == 0) {
            for (int e = threadIdx.x; e < DIM; e += 256) {
                float s = bout[e];
                for (int c = 0; c < HEADS*DIM; c++) s += bo[c & 127] * Wout[c*DIM + e];
                g_bfinal[e] = s;
            }
        }
    }
}

// ---------------- split precomputed weights into bf16 hi/lo ----------------
__global__ void splitW_kernel()
{
    int i = blockIdx.x * 256 + threadIdx.x;   // i < 131072
    {
        float v = g_M[i];
        __nv_bfloat16 hi = __float2bfloat16(v);
        g_Mhi[i] = hi;
        g_Mlo[i] = __float2bfloat16(v - __bfloat162float(hi));
    }
    {
        float v = g_W3[i];
        __nv_bfloat16 hi = __float2bfloat16(v);
        g_W3hi[i] = hi;
        g_W3lo[i] = __float2bfloat16(v - __bfloat162float(hi));
    }
}

// ---------------- layernorm + bf16 split -----------------------------------
__global__ void ln_kernel(const float* __restrict__ x, const float* __restrict__ g,
                          const float* __restrict__ b)
{
    int row = blockIdx.x;
    int d = threadIdx.x;
    float v = x[row*DIM + d];
    float s = v, s2 = v*v;
#pragma unroll
    for (int o = 16; o > 0; o >>= 1) {
        s  += __shfl_xor_sync(0xffffffffu, s, o);
        s2 += __shfl_xor_sync(0xffffffffu, s2, o);
    }
    __shared__ float ws[4], ws2[4];
    if ((d & 31) == 0) { ws[d >> 5] = s; ws2[d >> 5] = s2; }
    __syncthreads();
    float S  = ws[0] + ws[1] + ws[2] + ws[3];
    float S2 = ws2[0] + ws2[1] + ws2[2] + ws2[3];
    float mu = S * (1.f/128.f);
    float var = S2 * (1.f/128.f) - mu*mu;
    float inv = rsqrtf(var + 1e-5f);
    float xn = (v - mu) * inv * g[d] + b[d];
    g_xn[row*DIM + d] = xn;
    __nv_bfloat16 hi = __float2bfloat16(xn);
    g_XNhi[row*DIM + d] = hi;
    g_XNlo[row*DIM + d] = __float2bfloat16(xn - __bfloat162float(hi));
}

// ---------------- integral image: batched-load register scans --------------
__global__ void rowcum_kernel()
{
    int bh = blockIdx.x;        // b*32 + h
    int d = threadIdx.x;
    float v[GRID];
#pragma unroll
    for (int w = 0; w < GRID; w++) v[w] = g_xn[(bh*GRID + w)*DIM + d];
    float run = 0.f;
#pragma unroll
    for (int w = 0; w < GRID; w++) {
        run += v[w];
        g_S[(bh*GRID + w)*DIM + d] = run;
    }
}

__global__ void colcum_kernel()
{
    int b = blockIdx.x >> 5, w = blockIdx.x & 31;
    int d = threadIdx.x;
    float v[GRID];
#pragma unroll
    for (int h = 0; h < GRID; h++) v[h] = g_S[((b*GRID + h)*GRID + w)*DIM + d];
    float run = 0.f;
#pragma unroll
    for (int h = 0; h < GRID; h++) {
        run += v[h];
        g_S[((b*GRID + h)*GRID + w)*DIM + d] = run;
    }
}

// ---------------- region means ---------------------------------------------
__global__ void regions_kernel()
{
    int pos = blockIdx.x;                 // b*1024 + h*32 + w
    int b = pos >> 10;
    int hw = pos & 1023;
    int h = hw >> 5, w = hw & 31;
    int d = threadIdx.x;
    const float* Sb = g_S + b*GRID*GRID*DIM;
#define SS(hh,ww) (((hh) < 0 || (ww) < 0) ? 0.f : Sb[((hh)*GRID + (ww))*DIM + d])
    float s_hw  = SS(h, w);
    float s_hW  = SS(h, GRID-1);
    float s_Hw  = SS(GRID-1, w);
    float s_HW  = SS(GRID-1, GRID-1);
    float s_h1w1 = SS(h-1, w-1);
    float s_h1w  = SS(h-1, w);
    float s_hw1  = SS(h, w-1);
    float s_h1W  = SS(h-1, GRID-1);
    float s_Hw1  = SS(GRID-1, w-1);
#undef SS
    float hp1 = (float)(h+1), wp1 = (float)(w+1);
    float hr = (float)(GRID - h), wr = (float)(GRID - w);
    float* R = g_regions + pos*4*DIM;
    R[0*DIM + d] = s_hw / (hp1*wp1);
    R[1*DIM + d] = (s_hW - s_hw1) / (hp1*wr);
    R[2*DIM + d] = (s_Hw - s_h1w) / (hr*wp1);
    R[3*DIM + d] = (s_HW - s_h1W - s_Hw1 + s_h1w1) / (hr*wr);
}

// ---------------- tensor-core GEMM: U = XN @ Mcat + bu ----------------------
// A split [8192,128] hi/lo, B split [128,1024] hi/lo; 3-term K=384 bf16 GEMM.
__global__ __launch_bounds__(256) void gemmU_kernel()
{
    __shared__ __nv_bfloat16 As[128*24];   // 128 rows x 16 k, stride 24 (pad)
    __shared__ __nv_bfloat16 Bs[16*136];   // 16 k x 128 n, stride 136 (pad)
    const int tid = threadIdx.x;
    const int wid = tid >> 5, lane = tid & 31;
    const int wm = wid & 1, wn = wid >> 1;          // warp tile 64x32
    const int m0 = blockIdx.x * 128, n0 = blockIdx.y * 128;

    float acc[4][4][4];
#pragma unroll
    for (int mt = 0; mt < 4; mt++)
#pragma unroll
        for (int nt = 0; nt < 4; nt++)
#pragma unroll
            for (int q = 0; q < 4; q++) acc[mt][nt][q] = 0.f;

    const int arow = tid >> 1, ahalf = (tid & 1) * 8;
    const int bk = tid >> 4, bn = (tid & 15) * 8;

    unsigned a_addr[4], b_addr[4];
    {
        unsigned as_base = smem_u32(As);
        unsigned bs_base = smem_u32(Bs);
#pragma unroll
        for (int mt = 0; mt < 4; mt++)
            a_addr[mt] = as_base + ((wm*64 + mt*16 + (lane & 15))*24 + (lane >> 4)*8)*2;
#pragma unroll
        for (int nt = 0; nt < 4; nt++)
            b_addr[nt] = bs_base + ((lane & 15)*136 + wn*32 + nt*8)*2;
    }

    for (int kt = 0; kt < 24; kt++) {
        int seg = kt >> 3;            // 0: hi*hi, 1: hi*lo, 2: lo*hi
        int k0 = (kt & 7) * 16;
        const __nv_bfloat16* A = (seg == 2) ? g_XNlo : g_XNhi;
        const __nv_bfloat16* B = (seg == 1) ? g_Mlo  : g_Mhi;

        *(uint4*)&As[arow*24 + ahalf] = *(const uint4*)&A[(m0 + arow)*DIM + k0 + ahalf];
        *(uint4*)&Bs[bk*136 + bn]     = *(const uint4*)&B[(k0 + bk)*(HEADS*DIM) + n0 + bn];
        __syncthreads();

        unsigned af[4][4];
#pragma unroll
        for (int mt = 0; mt < 4; mt++) ldmatrix_x4(af[mt], a_addr[mt]);
#pragma unroll
        for (int nt = 0; nt < 4; nt++) {
            unsigned bf[2];
            ldmatrix_x2t(bf, b_addr[nt]);
#pragma unroll
            for (int mt = 0; mt < 4; mt++) mma_bf16(acc[mt][nt], af[mt], bf);
        }
        __syncthreads();
    }

    const int r0 = m0 + wm*64, c0 = n0 + wn*32;
    const int tr = lane >> 2, tc = (lane & 3)*2;
#pragma unroll
    for (int mt = 0; mt < 4; mt++)
#pragma unroll
        for (int nt = 0; nt < 4; nt++) {
            int row = r0 + mt*16 + tr, col = c0 + nt*8 + tc;
            g_U[row*(HEADS*DIM) + col]       = acc[mt][nt][0] + g_bu[col];
            g_U[row*(HEADS*DIM) + col + 1]   = acc[mt][nt][1] + g_bu[col + 1];
            g_U[(row+8)*(HEADS*DIM) + col]   = acc[mt][nt][2] + g_bu[col];
            g_U[(row+8)*(HEADS*DIM) + col+1] = acc[mt][nt][3] + g_bu[col + 1];
        }
}

// ---------------- softmax over 4 regions + aggregation (writes bf16 split) -
__global__ void attn_kernel()
{
    int pos = blockIdx.x;
    int tid = threadIdx.x;
    __shared__ float u[HEADS*DIM];
    __shared__ float reg[4][DIM];
    __shared__ float prob[HEADS][4];

    for (int t = tid; t < HEADS*DIM; t += 256) u[t] = g_U[pos*HEADS*DIM + t];
    for (int t = tid; t < 4*DIM; t += 256) reg[t >> 7][t & 127] = g_regions[pos*4*DIM + t];
    __syncthreads();

    int wid = tid >> 5, lane = tid & 31;   // 8 warps = 8 heads
    float d0 = 0.f, d1 = 0.f, d2 = 0.f, d3 = 0.f;
    const float* uh = u + wid*DIM;
#pragma unroll
    for (int dd = lane; dd < DIM; dd += 32) {
        float uv = uh[dd];
        d0 += uv * reg[0][dd];
        d1 += uv * reg[1][dd];
        d2 += uv * reg[2][dd];
        d3 += uv * reg[3][dd];
    }
#pragma unroll
    for (int o = 16; o > 0; o >>= 1) {
        d0 += __shfl_xor_sync(0xffffffffu, d0, o);
        d1 += __shfl_xor_sync(0xffffffffu, d1, o);
        d2 += __shfl_xor_sync(0xffffffffu, d2, o);
        d3 += __shfl_xor_sync(0xffffffffu, d3, o);
    }
    if (lane == 0) {
        const float scale = 0.25f;   // (dim/heads)^-0.5 = 16^-0.5
        float s0 = d0*scale, s1 = d1*scale, s2 = d2*scale, s3 = d3*scale;
        float m = fmaxf(fmaxf(s0, s1), fmaxf(s2, s3));
        float e0 = expf(s0 - m), e1 = expf(s1 - m), e2 = expf(s2 - m), e3 = expf(s3 - m);
        float inv = 1.f / (e0 + e1 + e2 + e3);
        prob[wid][0] = e0*inv; prob[wid][1] = e1*inv;
        prob[wid][2] = e2*inv; prob[wid][3] = e3*inv;
    }
    __syncthreads();

    for (int t = tid; t < HEADS*DIM; t += 256) {
        int h = t >> 7, dd = t & 127;
        float c = prob[h][0]*reg[0][dd] + prob[h][1]*reg[1][dd]
                + prob[h][2]*reg[2][dd] + prob[h][3]*reg[3][dd];
        __nv_bfloat16 hi = __float2bfloat16(c);
        g_Chi[pos*HEADS*DIM + t] = hi;
        g_Clo[pos*HEADS*DIM + t] = __float2bfloat16(c - __bfloat162float(hi));
    }
}

// ---------------- tensor-core GEMM: Yp[h] = C_h @ W3_h ----------------------
__global__ __launch_bounds__(256) void gemmY_kernel()
{
    __shared__ __nv_bfloat16 As[128*24];
    __shared__ __nv_bfloat16 Bs[16*136];
    const int tid = threadIdx.x;
    const int wid = tid >> 5, lane = tid & 31;
    const int wm = wid & 1, wn = wid >> 1;
    const int m0 = blockIdx.x * 128;
    const int h = blockIdx.z;

    float acc[4][4][4];
#pragma unroll
    for (int mt = 0; mt < 4; mt++)
#pragma unroll
        for (int nt = 0; nt < 4; nt++)
#pragma unroll
            for (int q = 0; q < 4; q++) acc[mt][nt][q] = 0.f;

    const int arow = tid >> 1, ahalf = (tid & 1) * 8;
    const int bk = tid >> 4, bn = (tid & 15) * 8;

    unsigned a_addr[4], b_addr[4];
    {
        unsigned as_base = smem_u32(As);
        unsigned bs_base = smem_u32(Bs);
#pragma unroll
        for (int mt = 0; mt < 4; mt++)
            a_addr[mt] = as_base + ((wm*64 + mt*16 + (lane & 15))*24 + (lane >> 4)*8)*2;
#pragma unroll
        for (int nt = 0; nt < 4; nt++)
            b_addr[nt] = bs_base + ((lane & 15)*136 + wn*32 + nt*8)*2;
    }

    for (int kt = 0; kt < 24; kt++) {
        int seg = kt >> 3;
        int k0 = (kt & 7) * 16;
        const __nv_bfloat16* A = ((seg == 2) ? g_Clo : g_Chi) + h*DIM;      // lda 1024
        const __nv_bfloat16* B = ((seg == 1) ? g_W3lo : g_W3hi) + h*DIM*DIM; // ldb 128

        *(uint4*)&As[arow*24 + ahalf] = *(const uint4*)&A[(m0 + arow)*(HEADS*DIM) + k0 + ahalf];
        *(uint4*)&Bs[bk*136 + bn]     = *(const uint4*)&B[(k0 + bk)*DIM + bn];
        __syncthreads();

        unsigned af[4][4];
#pragma unroll
        for (int mt = 0; mt < 4; mt++) ldmatrix_x4(af[mt], a_addr[mt]);
#pragma unroll
        for (int nt = 0; nt < 4; nt++) {
            unsigned bf[2];
            ldmatrix_x2t(bf, b_addr[nt]);
#pragma unroll
            for (int mt = 0; mt < 4; mt++) mma_bf16(acc[mt][nt], af[mt], bf);
        }
        __syncthreads();
    }

    float* Cdst = g_Yp + h*POSITIONS*DIM;
    const int r0 = m0 + wm*64, c0 = wn*32;
    const int tr = lane >> 2, tc = (lane & 3)*2;
#pragma unroll
    for (int mt = 0; mt < 4; mt++)
#pragma unroll
        for (int nt = 0; nt < 4; nt++) {
            int row = r0 + mt*16 + tr, col = c0 + nt*8 + tc;
            Cdst[row*DIM + col]       = acc[mt][nt][0];
            Cdst[row*DIM + col + 1]   = acc[mt][nt][1];
            Cdst[(row+8)*DIM + col]   = acc[mt][nt][2];
            Cdst[(row+8)*DIM + col+1] = acc[mt][nt][3];
        }
}

// ---------------- final reduction over heads + bias ------------------------
__global__ void reduceY_kernel(float* __restrict__ out)
{
    int i = blockIdx.x * 256 + threadIdx.x;   // i < 8192*128
    float s = g_bfinal[i & 127];
#pragma unroll
    for (int h = 0; h < HEADS; h++) s += g_Yp[h*POSITIONS*DIM + i];
    out[i] = s;
}

// ---------------- launch ----------------------------------------------------
extern "C" void kernel_launch(void* const* d_in, const int* in_sizes, int n_in,
                              void* d_out, int out_size)
{
    const float* x    = (const float*)d_in[0];
    const float* ln_g = (const float*)d_in[1];
    const float* ln_b = (const float*)d_in[2];
    const float* Wqkv = (const float*)d_in[3];
    const float* bqkv = (const float*)d_in[4];
    const float* Wq   = (const float*)d_in[5];
    const float* Wk   = (const float*)d_in[6];
    const float* Wv   = (const float*)d_in[7];
    const float* Wo   = (const float*)d_in[8];
    const float* bo   = (const float*)d_in[9];
    const float* Wout = (const float*)d_in[10];
    const float* bout = (const float*)d_in[11];
    float* out = (float*)d_out;

    precompA_kernel<<<16, 256>>>(Wqkv, bqkv, Wq, Wo, Wout);
    precompB_kernel<<<16, 256>>>(Wk, Wv, Wout, bo, bout);
    splitW_kernel<<<512, 256>>>();
    ln_kernel<<<POSITIONS, 128>>>(x, ln_g, ln_b);
    rowcum_kernel<<<BATCH*GRID, 128>>>();
    colcum_kernel<<<BATCH*GRID, 128>>>();
    regions_kernel<<<POSITIONS, 128>>>();
    gemmU_kernel<<<dim3(POSITIONS/128, HEADS, 1), 256>>>();
    attn_kernel<<<POSITIONS, 256>>>();
    gemmY_kernel<<<dim3(POSITIONS/128, 1, HEADS), 256>>>();
    reduceY_kernel<<<POSITIONS*DIM/256, 256>>>(out);
}

// round 3
// speedup vs baseline: 1.7532x; 1.1507x over previous
#include <cuda_runtime.h>
#include <cuda_bf16.h>
#include <math.h>

// Problem constants
#define BATCH 8
#define NPOS 1024            // 32x32
#define DIM 128
#define HEADS 8
#define GRID 32              // H = W = 32
#define POSITIONS (BATCH*NPOS)   // 8192

#define GEMM_SMEM 71680      // 2x(128x72) + 2x(64x136) bf16; also holds 128x132 f32 U tile

// ---------------- scratch (static device memory; no allocs allowed) -------
__device__ float g_xn[POSITIONS*DIM];
__device__ float g_S[POSITIONS*DIM];
__device__ float g_regions[POSITIONS*4*DIM];
__device__ float g_Wf[HEADS*DIM*DIM];            // Wqkv_h @ Wq (fp32, stage A->B)
__device__ float g_T[HEADS*DIM*DIM];             // Wo @ Wout_h (fp32, stage A->B)
__device__ float g_bf[HEADS*DIM];
__device__ float g_bu[HEADS*DIM];
__device__ float g_bfinal[DIM];
__device__ float g_Yp[HEADS*POSITIONS*DIM];

// bf16 split buffers (x = hi + lo)
__device__ __nv_bfloat16 g_XNhi[POSITIONS*DIM];
__device__ __nv_bfloat16 g_XNlo[POSITIONS*DIM];
__device__ __nv_bfloat16 g_Mhi[DIM*HEADS*DIM];   // [128][1024]
__device__ __nv_bfloat16 g_Mlo[DIM*HEADS*DIM];
__device__ __nv_bfloat16 g_W3hi[HEADS*DIM*DIM];  // per-head [128][128]
__device__ __nv_bfloat16 g_W3lo[HEADS*DIM*DIM];
__device__ __nv_bfloat16 g_Chi[POSITIONS*HEADS*DIM];
__device__ __nv_bfloat16 g_Clo[POSITIONS*HEADS*DIM];

// ---------------- helpers ---------------------------------------------------
__device__ __forceinline__ unsigned smem_u32(const void* p) {
    return (unsigned)__cvta_generic_to_shared(p);
}
__device__ __forceinline__ void ldmatrix_x4(unsigned* r, unsigned addr) {
    asm volatile("ldmatrix.sync.aligned.m8n8.x4.shared.b16 {%0,%1,%2,%3}, [%4];"
        : "=r"(r[0]), "=r"(r[1]), "=r"(r[2]), "=r"(r[3]) : "r"(addr));
}
__device__ __forceinline__ void ldmatrix_x2t(unsigned* r, unsigned addr) {
    asm volatile("ldmatrix.sync.aligned.m8n8.x2.trans.shared.b16 {%0,%1}, [%2];"
        : "=r"(r[0]), "=r"(r[1]) : "r"(addr));
}
__device__ __forceinline__ void mma_bf16(float* d, const unsigned* a, const unsigned* b) {
    asm volatile("mma.sync.aligned.m16n8k16.row.col.f32.bf16.bf16.f32 "
        "{%0,%1,%2,%3}, {%4,%5,%6,%7}, {%8,%9}, {%0,%1,%2,%3};"
        : "+f"(d[0]), "+f"(d[1]), "+f"(d[2]), "+f"(d[3])
        : "r"(a[0]), "r"(a[1]), "r"(a[2]), "r"(a[3]), "r"(b[0]), "r"(b[1]));
}
__device__ __forceinline__ void cp_async16(void* smem_dst, const void* gsrc) {
    asm volatile("cp.async.ca.shared.global [%0], [%1], 16;"
        :: "r"(smem_u32(smem_dst)), "l"(gsrc));
}

// ---------------- 64x64-tile fp32 matmul for weight precompute --------------
// MODE 0: store fp32 to C; MODE 1: store bf16 hi/lo pair to Chi/Clo
template<int MODE>
__device__ void mm64(const float* __restrict__ A, int lda,
                     const float* __restrict__ B, int ldb, int transB,
                     float* __restrict__ C,
                     __nv_bfloat16* __restrict__ Chi, __nv_bfloat16* __restrict__ Clo,
                     int ldc, int row0, int col0)
{
    __shared__ float As[16][64];
    __shared__ float Bs[16][68];
    const int tid = threadIdx.x;
    const int ty = tid >> 4, tx = tid & 15;
    float acc[4][4];
#pragma unroll
    for (int i = 0; i < 4; i++)
#pragma unroll
        for (int j = 0; j < 4; j++) acc[i][j] = 0.f;

    for (int k0 = 0; k0 < 128; k0 += 16) {
        for (int t = tid; t < 1024; t += 256) {
            int m = t >> 4, kk = t & 15;
            As[kk][m] = A[(row0+m)*lda + k0 + kk];
        }
        for (int t = tid; t < 1024; t += 256) {
            int kk = t >> 6, n = t & 63;
            Bs[kk][n] = transB ? B[(col0+n)*ldb + k0 + kk] : B[(k0+kk)*ldb + col0 + n];
        }
        __syncthreads();
#pragma unroll
        for (int kk = 0; kk < 16; kk++) {
            float a[4], b[4];
#pragma unroll
            for (int i = 0; i < 4; i++) a[i] = As[kk][ty*4+i];
#pragma unroll
            for (int j = 0; j < 4; j++) b[j] = Bs[kk][tx*4+j];
#pragma unroll
            for (int i = 0; i < 4; i++)
#pragma unroll
                for (int j = 0; j < 4; j++) acc[i][j] += a[i]*b[j];
        }
        __syncthreads();
    }
#pragma unroll
    for (int i = 0; i < 4; i++)
#pragma unroll
        for (int j = 0; j < 4; j++) {
            int r = row0 + ty*4 + i, c = col0 + tx*4 + j;
            if (MODE == 0) {
                C[r*ldc + c] = acc[i][j];
            } else {
                float v = acc[i][j];
                __nv_bfloat16 hi = __float2bfloat16(v);
                Chi[r*ldc + c] = hi;
                Clo[r*ldc + c] = __float2bfloat16(v - __bfloat162float(hi));
            }
        }
}

// ---------------- weight precompute, stage A --------------------------------
__global__ void precompA2(const float* __restrict__ Wqkv, const float* __restrict__ bqkv,
                          const float* __restrict__ Wq, const float* __restrict__ Wo,
                          const float* __restrict__ Wout)
{
    int blk = blockIdx.x;
    if (blk < 32) {
        int h = blk >> 2, q = blk & 3;
        mm64<0>(Wqkv + h*128, 3*HEADS*DIM, Wq, DIM, 0,
                g_Wf + h*DIM*DIM, 0, 0, DIM, (q>>1)*64, (q&1)*64);
    } else if (blk < 64) {
        int h = (blk-32) >> 2, q = (blk-32) & 3;
        mm64<0>(Wo, DIM, Wout + h*DIM*DIM, DIM, 0,
                g_T + h*DIM*DIM, 0, 0, DIM, (q>>1)*64, (q&1)*64);
    } else {
        for (int o = threadIdx.x; o < HEADS*DIM; o += 256) {
            int h = o >> 7, e = o & 127;
            float s = 0.f;
#pragma unroll 8
            for (int c = 0; c < 128; c++) s += bqkv[h*128+c] * Wq[c*128+e];
            g_bf[o] = s;
        }
    }
}

// ---------------- weight precompute, stage B --------------------------------
__global__ void precompB2(const float* __restrict__ Wk, const float* __restrict__ Wv,
                          const float* __restrict__ Wout, const float* __restrict__ bo,
                          const float* __restrict__ bout)
{
    int blk = blockIdx.x;
    if (blk < 32) {
        int h = blk >> 2, q = blk & 3;
        // M_h = Wf_h @ Wk^T -> hi/lo at [row][h*128+col] (ldc 1024)
        mm64<1>(g_Wf + h*DIM*DIM, DIM, Wk, DIM, 1, 0,
                g_Mhi + h*DIM, g_Mlo + h*DIM, HEADS*DIM, (q>>1)*64, (q&1)*64);
    } else if (blk < 64) {
        int h = (blk-32) >> 2, q = (blk-32) & 3;
        // W3_h = Wv @ T_h -> hi/lo per-head [128][128]
        mm64<1>(Wv, DIM, g_T + h*DIM*DIM, DIM, 0, 0,
                g_W3hi + h*DIM*DIM, g_W3lo + h*DIM*DIM, DIM, (q>>1)*64, (q&1)*64);
    } else if (blk == 64) {
        for (int o = threadIdx.x; o < HEADS*DIM; o += 256) {
            int h = o >> 7, d2 = o & 127;
            float s = 0.f;
#pragma unroll 8
            for (int e = 0; e < 128; e++) s += g_bf[h*128+e] * Wk[d2*128+e];
            g_bu[o] = s;
        }
    } else {
        __shared__ float part[256];
        int e = threadIdx.x & 127, half = threadIdx.x >> 7;
        float s = 0.f;
#pragma unroll 8
        for (int c = half*512; c < half*512 + 512; c++) s += bo[c & 127] * Wout[c*128 + e];
        part[threadIdx.x] = s;
        __syncthreads();
        if (half == 0) g_bfinal[e] = part[e] + part[128+e] + bout[e];
    }
}

// ---------------- layernorm + bf16 split ------------------------------------
__global__ void ln_kernel(const float* __restrict__ x, const float* __restrict__ g,
                          const float* __restrict__ b)
{
    int row = blockIdx.x;
    int d = threadIdx.x;
    float v = x[row*DIM + d];
    float s = v, s2 = v*v;
#pragma unroll
    for (int o = 16; o > 0; o >>= 1) {
        s  += __shfl_xor_sync(0xffffffffu, s, o);
        s2 += __shfl_xor_sync(0xffffffffu, s2, o);
    }
    __shared__ float ws[4], ws2[4];
    if ((d & 31) == 0) { ws[d >> 5] = s; ws2[d >> 5] = s2; }
    __syncthreads();
    float S  = ws[0] + ws[1] + ws[2] + ws[3];
    float S2 = ws2[0] + ws2[1] + ws2[2] + ws2[3];
    float mu = S * (1.f/128.f);
    float var = S2 * (1.f/128.f) - mu*mu;
    float inv = rsqrtf(var + 1e-5f);
    float xn = (v - mu) * inv * g[d] + b[d];
    g_xn[row*DIM + d] = xn;
    __nv_bfloat16 hi = __float2bfloat16(xn);
    g_XNhi[row*DIM + d] = hi;
    g_XNlo[row*DIM + d] = __float2bfloat16(xn - __bfloat162float(hi));
}

// ---------------- integral image: batched-load register scans ---------------
__global__ void rowcum_kernel()
{
    int bh = blockIdx.x;
    int d = threadIdx.x;
    float v[GRID];
#pragma unroll
    for (int w = 0; w < GRID; w++) v[w] = g_xn[(bh*GRID + w)*DIM + d];
    float run = 0.f;
#pragma unroll
    for (int w = 0; w < GRID; w++) {
        run += v[w];
        g_S[(bh*GRID + w)*DIM + d] = run;
    }
}

__global__ void colcum_kernel()
{
    int b = blockIdx.x >> 5, w = blockIdx.x & 31;
    int d = threadIdx.x;
    float v[GRID];
#pragma unroll
    for (int h = 0; h < GRID; h++) v[h] = g_S[((b*GRID + h)*GRID + w)*DIM + d];
    float run = 0.f;
#pragma unroll
    for (int h = 0; h < GRID; h++) {
        run += v[h];
        g_S[((b*GRID + h)*GRID + w)*DIM + d] = run;
    }
}

// ---------------- region means ----------------------------------------------
__global__ void regions_kernel()
{
    int pos = blockIdx.x;
    int b = pos >> 10;
    int hw = pos & 1023;
    int h = hw >> 5, w = hw & 31;
    int d = threadIdx.x;
    const float* Sb = g_S + b*GRID*GRID*DIM;
#define SS(hh,ww) (((hh) < 0 || (ww) < 0) ? 0.f : Sb[((hh)*GRID + (ww))*DIM + d])
    float s_hw  = SS(h, w);
    float s_hW  = SS(h, GRID-1);
    float s_Hw  = SS(GRID-1, w);
    float s_HW  = SS(GRID-1, GRID-1);
    float s_h1w1 = SS(h-1, w-1);
    float s_h1w  = SS(h-1, w);
    float s_hw1  = SS(h, w-1);
    float s_h1W  = SS(h-1, GRID-1);
    float s_Hw1  = SS(GRID-1, w-1);
#undef SS
    float hp1 = (float)(h+1), wp1 = (float)(w+1);
    float hr = (float)(GRID - h), wr = (float)(GRID - w);
    float* R = g_regions + pos*4*DIM;
    R[0*DIM + d] = s_hw / (hp1*wp1);
    R[1*DIM + d] = (s_hW - s_hw1) / (hp1*wr);
    R[2*DIM + d] = (s_Hw - s_h1w) / (hr*wp1);
    R[3*DIM + d] = (s_HW - s_h1W - s_Hw1 + s_h1w1) / (hr*wr);
}

// ---------------- fused: U-GEMM + softmax + aggregate -> C hi/lo ------------
// Block: 128 positions x one head. 3-term bf16 K=384 GEMM with cp.async
// double buffering, then in-block per-(pos,head) 4-region softmax.
__global__ __launch_bounds__(256) void gemmU_fused()
{
    extern __shared__ char sbuf[];
    __nv_bfloat16* As = (__nv_bfloat16*)sbuf;               // 2 x 128x72
    __nv_bfloat16* Bs = (__nv_bfloat16*)(sbuf + 36864);     // 2 x 64x136
    float* Uf = (float*)sbuf;                               // 128x132 (aliases A/B)

    const int tid = threadIdx.x;
    const int wid = tid >> 5, lane = tid & 31;
    const int wm = wid & 1, wn = wid >> 1;                  // warp tile 64x32
    const int m0 = blockIdx.x * 128;
    const int h  = blockIdx.y;
    const int n0 = h * 128;

    const __nv_bfloat16* Aseg[3] = {g_XNhi, g_XNhi, g_XNlo};
    const __nv_bfloat16* Bseg[3] = {g_Mhi, g_Mlo, g_Mhi};

    float acc[4][4][4];
#pragma unroll
    for (int mt = 0; mt < 4; mt++)
#pragma unroll
        for (int nt = 0; nt < 4; nt++)
#pragma unroll
            for (int q = 0; q < 4; q++) acc[mt][nt][q] = 0.f;

    auto LOAD = [&](int s, int buf) {
        int seg = s >> 1, k0 = (s & 1) * 64;
        const __nv_bfloat16* Ag = Aseg[seg];
        const __nv_bfloat16* Bg = Bseg[seg];
#pragma unroll
        for (int i = 0; i < 4; i++) {
            int c = tid + i*256;
            int row = c >> 3, col8 = (c & 7) * 8;
            cp_async16(As + buf*9216 + row*72 + col8,
                       Ag + (m0+row)*DIM + k0 + col8);
        }
#pragma unroll
        for (int i = 0; i < 4; i++) {
            int c = tid + i*256;
            int kr = c >> 4, col8 = (c & 15) * 8;
            cp_async16(Bs + buf*8704 + kr*136 + col8,
                       Bg + (k0+kr)*(HEADS*DIM) + n0 + col8);
        }
        asm volatile("cp.async.commit_group;");
    };

    const unsigned as_base = smem_u32(As), bs_base = smem_u32(Bs);
    unsigned a_off[4], b_off[4];
#pragma unroll
    for (int mt = 0; mt < 4; mt++)
        a_off[mt] = ((wm*64 + mt*16 + (lane & 15))*72 + (lane >> 4)*8)*2;
#pragma unroll
    for (int nt = 0; nt < 4; nt++)
        b_off[nt] = ((lane & 15)*136 + wn*32 + nt*8)*2;

    auto COMPUTE = [&](int buf) {
#pragma unroll
        for (int kk = 0; kk < 4; kk++) {
            unsigned af[4][4];
#pragma unroll
            for (int mt = 0; mt < 4; mt++)
                ldmatrix_x4(af[mt], as_base + buf*18432 + a_off[mt] + kk*32);
#pragma unroll
            for (int nt = 0; nt < 4; nt++) {
                unsigned bfr[2];
                ldmatrix_x2t(bfr, bs_base + buf*17408 + b_off[nt] + kk*4352);
#pragma unroll
                for (int mt = 0; mt < 4; mt++) mma_bf16(acc[mt][nt], af[mt], bfr);
            }
        }
    };

    LOAD(0, 0);
    for (int s = 0; s < 6; s++) {
        int cur = s & 1;
        if (s < 5) {
            LOAD(s+1, cur^1);
            asm volatile("cp.async.wait_group 1;");
        } else {
            asm volatile("cp.async.wait_group 0;");
        }
        __syncthreads();
        COMPUTE(cur);
        __syncthreads();
    }

    // ---- write U tile (acc + bias) into smem fp32 -------------------------
    const int tr = lane >> 2, tc = (lane & 3)*2;
    const int r0 = wm*64, c0 = wn*32;
#pragma unroll
    for (int mt = 0; mt < 4; mt++)
#pragma unroll
        for (int nt = 0; nt < 4; nt++) {
            int row = r0 + mt*16 + tr, col = c0 + nt*8 + tc;
            float b0 = g_bu[n0 + col], b1 = g_bu[n0 + col + 1];
            *(float2*)&Uf[row*132 + col] =
                make_float2(acc[mt][nt][0] + b0, acc[mt][nt][1] + b1);
            *(float2*)&Uf[(row+8)*132 + col] =
                make_float2(acc[mt][nt][2] + b0, acc[mt][nt][3] + b1);
        }
    __syncthreads();

    // ---- per-warp: scores, softmax, aggregate, write C hi/lo --------------
    for (int i = 0; i < 16; i++) {
        int p = wid*16 + i;
        int gpos = m0 + p;
        const float* Rp = g_regions + (size_t)gpos*4*DIM;
        float s0 = 0.f, s1 = 0.f, s2 = 0.f, s3 = 0.f;
#pragma unroll
        for (int c2 = 0; c2 < 4; c2++) {
            int d = lane + c2*32;
            float u = Uf[p*132 + d];
            s0 += u * Rp[d];
            s1 += u * Rp[DIM + d];
            s2 += u * Rp[2*DIM + d];
            s3 += u * Rp[3*DIM + d];
        }
#pragma unroll
        for (int o = 16; o > 0; o >>= 1) {
            s0 += __shfl_xor_sync(0xffffffffu, s0, o);
            s1 += __shfl_xor_sync(0xffffffffu, s1, o);
            s2 += __shfl_xor_sync(0xffffffffu, s2, o);
            s3 += __shfl_xor_sync(0xffffffffu, s3, o);
        }
        s0 *= 0.25f; s1 *= 0.25f; s2 *= 0.25f; s3 *= 0.25f;
        float m = fmaxf(fmaxf(s0, s1), fmaxf(s2, s3));
        float e0 = expf(s0 - m), e1 = expf(s1 - m), e2 = expf(s2 - m), e3 = expf(s3 - m);
        float inv = 1.f / (e0 + e1 + e2 + e3);
        float p0 = e0*inv, p1 = e1*inv, p2 = e2*inv, p3 = e3*inv;
#pragma unroll
        for (int c2 = 0; c2 < 4; c2++) {
            int d = lane + c2*32;
            float cv = p0*Rp[d] + p1*Rp[DIM + d] + p2*Rp[2*DIM + d] + p3*Rp[3*DIM + d];
            __nv_bfloat16 hi = __float2bfloat16(cv);
            g_Chi[(size_t)gpos*(HEADS*DIM) + n0 + d] = hi;
            g_Clo[(size_t)gpos*(HEADS*DIM) + n0 + d] = __float2bfloat16(cv - __bfloat162float(hi));
        }
    }
}

// ---------------- Yp[h] = C_h @ W3_h  (cp.async double-buffered) ------------
__global__ __launch_bounds__(256) void gemmY2()
{
    extern __shared__ char sbuf[];
    __nv_bfloat16* As = (__nv_bfloat16*)sbuf;
    __nv_bfloat16* Bs = (__nv_bfloat16*)(sbuf + 36864);

    const int tid = threadIdx.x;
    const int wid = tid >> 5, lane = tid & 31;
    const int wm = wid & 1, wn = wid >> 1;
    const int m0 = blockIdx.x * 128;
    const int h  = blockIdx.z;

    const __nv_bfloat16* Aseg[3] = {g_Chi, g_Chi, g_Clo};
    const __nv_bfloat16* Bseg[3] = {g_W3hi, g_W3lo, g_W3hi};

    float acc[4][4][4];
#pragma unroll
    for (int mt = 0; mt < 4; mt++)
#pragma unroll
        for (int nt = 0; nt < 4; nt++)
#pragma unroll
            for (int q = 0; q < 4; q++) acc[mt][nt][q] = 0.f;

    auto LOAD = [&](int s, int buf) {
        int seg = s >> 1, k0 = (s & 1) * 64;
        const __nv_bfloat16* Ag = Aseg[seg] + h*DIM;           // lda 1024
        const __nv_bfloat16* Bg = Bseg[seg] + h*DIM*DIM;       // ldb 128
#pragma unroll
        for (int i = 0; i < 4; i++) {
            int c = tid + i*256;
            int row = c >> 3, col8 = (c & 7) * 8;
            cp_async16(As + buf*9216 + row*72 + col8,
                       Ag + (size_t)(m0+row)*(HEADS*DIM) + k0 + col8);
        }
#pragma unroll
        for (int i = 0; i < 4; i++) {
            int c = tid + i*256;
            int kr = c >> 4, col8 = (c & 15) * 8;
            cp_async16(Bs + buf*8704 + kr*136 + col8,
                       Bg + (k0+kr)*DIM + col8);
        }
        asm volatile("cp.async.commit_group;");
    };

    const unsigned as_base = smem_u32(As), bs_base = smem_u32(Bs);
    unsigned a_off[4], b_off[4];
#pragma unroll
    for (int mt = 0; mt < 4; mt++)
        a_off[mt] = ((wm*64 + mt*16 + (lane & 15))*72 + (lane >> 4)*8)*2;
#pragma unroll
    for (int nt = 0; nt < 4; nt++)
        b_off[nt] = ((lane & 15)*136 + wn*32 + nt*8)*2;

    auto COMPUTE = [&](int buf) {
#pragma unroll
        for (int kk = 0; kk < 4; kk++) {
            unsigned af[4][4];
#pragma unroll
            for (int mt = 0; mt < 4; mt++)
                ldmatrix_x4(af[mt], as_base + buf*18432 + a_off[mt] + kk*32);
#pragma unroll
            for (int nt = 0; nt < 4; nt++) {
                unsigned bfr[2];
                ldmatrix_x2t(bfr, bs_base + buf*17408 + b_off[nt] + kk*4352);
#pragma unroll
                for (int mt = 0; mt < 4; mt++) mma_bf16(acc[mt][nt], af[mt], bfr);
            }
        }
    };

    LOAD(0, 0);
    for (int s = 0; s < 6; s++) {
        int cur = s & 1;
        if (s < 5) {
            LOAD(s+1, cur^1);
            asm volatile("cp.async.wait_group 1;");
        } else {
            asm volatile("cp.async.wait_group 0;");
        }
        __syncthreads();
        COMPUTE(cur);
        __syncthreads();
    }

    float* Cdst = g_Yp + (size_t)h*POSITIONS*DIM;
    const int r0 = m0 + wm*64, c0 = wn*32;
    const int tr = lane >> 2, tc = (lane & 3)*2;
#pragma unroll
    for (int mt = 0; mt < 4; mt++)
#pragma unroll
        for (int nt = 0; nt < 4; nt++) {
            int row = r0 + mt*16 + tr, col = c0 + nt*8 + tc;
            *(float2*)&Cdst[(size_t)row*DIM + col] =
                make_float2(acc[mt][nt][0], acc[mt][nt][1]);
            *(float2*)&Cdst[(size_t)(row+8)*DIM + col] =
                make_float2(acc[mt][nt][2], acc[mt][nt][3]);
        }
}

// ---------------- final reduction over heads + bias -------------------------
__global__ void reduceY_kernel(float* __restrict__ out)
{
    int i = blockIdx.x * 256 + threadIdx.x;
    float s = g_bfinal[i & 127];
#pragma unroll
    for (int h = 0; h < HEADS; h++) s += g_Yp[(size_t)h*POSITIONS*DIM + i];
    out[i] = s;
}

// ---------------- launch -----------------------------------------------------
extern "C" void kernel_launch(void* const* d_in, const int* in_sizes, int n_in,
                              void* d_out, int out_size)
{
    const float* x    = (const float*)d_in[0];
    const float* ln_g = (const float*)d_in[1];
    const float* ln_b = (const float*)d_in[2];
    const float* Wqkv = (const float*)d_in[3];
    const float* bqkv = (const float*)d_in[4];
    const float* Wq   = (const float*)d_in[5];
    const float* Wk   = (const float*)d_in[6];
    const float* Wv   = (const float*)d_in[7];
    const float* Wo   = (const float*)d_in[8];
    const float* bo   = (const float*)d_in[9];
    const float* Wout = (const float*)d_in[10];
    const float* bout = (const float*)d_in[11];
    float* out = (float*)d_out;

    cudaFuncSetAttribute(gemmU_fused, cudaFuncAttributeMaxDynamicSharedMemorySize, GEMM_SMEM);
    cudaFuncSetAttribute(gemmY2,      cudaFuncAttributeMaxDynamicSharedMemorySize, GEMM_SMEM);

    precompA2<<<65, 256>>>(Wqkv, bqkv, Wq, Wo, Wout);
    precompB2<<<66, 256>>>(Wk, Wv, Wout, bo, bout);
    ln_kernel<<<POSITIONS, 128>>>(x, ln_g, ln_b);
    rowcum_kernel<<<BATCH*GRID, 128>>>();
    colcum_kernel<<<BATCH*GRID, 128>>>();
    regions_kernel<<<POSITIONS, 128>>>();
    gemmU_fused<<<dim3(POSITIONS/128, HEADS), 256, GEMM_SMEM>>>();
    gemmY2<<<dim3(POSITIONS/128, 1, HEADS), 256, GEMM_SMEM>>>();
    reduceY_kernel<<<POSITIONS*DIM/256, 256>>>(out);
}

// round 4
// speedup vs baseline: 2.4988x; 1.4253x over previous
#include <cuda_runtime.h>
#include <cuda_fp16.h>
#include <math.h>

// Problem constants
#define BATCH 8
#define NPOS 1024            // 32x32
#define DIM 128
#define HEADS 8
#define GRID 32              // H = W = 32
#define POSITIONS (BATCH*NPOS)   // 8192

#define GEMM_SMEM 71680      // gemmU: 2x(128x72) + 2x(64x136) halfs; aliases 128x132 f32 U tile
#define GEMMY_SMEM 53248     // gemmY: 2x(64x72) + 2x(64x136) halfs

// ---------------- scratch (static device memory; no allocs allowed) -------
__device__ float g_xn[POSITIONS*DIM];
__device__ float g_S[POSITIONS*DIM];
__device__ float g_regions[POSITIONS*4*DIM];
__device__ float g_Wf[HEADS*DIM*DIM];            // Wqkv_h @ Wq (fp32, stage A->B)
__device__ float g_T[HEADS*DIM*DIM];             // Wo @ Wout_h (fp32, stage A->B)
__device__ float g_bf[HEADS*DIM];
__device__ float g_bu[HEADS*DIM];
__device__ float g_bfinal[DIM];

// fp16 GEMM operands
__device__ __half g_XNh[POSITIONS*DIM];          // [8192][128]
__device__ __half g_Mh[DIM*HEADS*DIM];           // [128][1024]
__device__ __half g_W3h[HEADS*DIM*DIM];          // [1024][128] (head-major rows)
__device__ __half g_Ch[POSITIONS*HEADS*DIM];     // [8192][1024]

// ---------------- helpers ---------------------------------------------------
__device__ __forceinline__ unsigned smem_u32(const void* p) {
    return (unsigned)__cvta_generic_to_shared(p);
}
__device__ __forceinline__ void ldmatrix_x4(unsigned* r, unsigned addr) {
    asm volatile("ldmatrix.sync.aligned.m8n8.x4.shared.b16 {%0,%1,%2,%3}, [%4];"
        : "=r"(r[0]), "=r"(r[1]), "=r"(r[2]), "=r"(r[3]) : "r"(addr));
}
__device__ __forceinline__ void ldmatrix_x2t(unsigned* r, unsigned addr) {
    asm volatile("ldmatrix.sync.aligned.m8n8.x2.trans.shared.b16 {%0,%1}, [%2];"
        : "=r"(r[0]), "=r"(r[1]) : "r"(addr));
}
__device__ __forceinline__ void mma_f16(float* d, const unsigned* a, const unsigned* b) {
    asm volatile("mma.sync.aligned.m16n8k16.row.col.f32.f16.f16.f32 "
        "{%0,%1,%2,%3}, {%4,%5,%6,%7}, {%8,%9}, {%0,%1,%2,%3};"
        : "+f"(d[0]), "+f"(d[1]), "+f"(d[2]), "+f"(d[3])
        : "r"(a[0]), "r"(a[1]), "r"(a[2]), "r"(a[3]), "r"(b[0]), "r"(b[1]));
}
__device__ __forceinline__ void cp_async16(void* smem_dst, const void* gsrc) {
    asm volatile("cp.async.ca.shared.global [%0], [%1], 16;"
        :: "r"(smem_u32(smem_dst)), "l"(gsrc));
}

// ---------------- 64x64-tile fp32 matmul for weight precompute --------------
// MODE 0: store fp32; MODE 1: store fp16
template<int MODE>
__device__ void mm64(const float* __restrict__ A, int lda,
                     const float* __restrict__ B, int ldb, int transB,
                     float* __restrict__ C, __half* __restrict__ Ch,
                     int ldc, int row0, int col0)
{
    __shared__ float As[16][64];
    __shared__ float Bs[16][68];
    const int tid = threadIdx.x;
    const int ty = tid >> 4, tx = tid & 15;
    float acc[4][4];
#pragma unroll
    for (int i = 0; i < 4; i++)
#pragma unroll
        for (int j = 0; j < 4; j++) acc[i][j] = 0.f;

    for (int k0 = 0; k0 < 128; k0 += 16) {
        for (int t = tid; t < 1024; t += 256) {
            int m = t >> 4, kk = t & 15;
            As[kk][m] = A[(row0+m)*lda + k0 + kk];
        }
        for (int t = tid; t < 1024; t += 256) {
            int kk = t >> 6, n = t & 63;
            Bs[kk][n] = transB ? B[(col0+n)*ldb + k0 + kk] : B[(k0+kk)*ldb + col0 + n];
        }
        __syncthreads();
#pragma unroll
        for (int kk = 0; kk < 16; kk++) {
            float a[4], b[4];
#pragma unroll
            for (int i = 0; i < 4; i++) a[i] = As[kk][ty*4+i];
#pragma unroll
            for (int j = 0; j < 4; j++) b[j] = Bs[kk][tx*4+j];
#pragma unroll
            for (int i = 0; i < 4; i++)
#pragma unroll
                for (int j = 0; j < 4; j++) acc[i][j] += a[i]*b[j];
        }
        __syncthreads();
    }
#pragma unroll
    for (int i = 0; i < 4; i++)
#pragma unroll
        for (int j = 0; j < 4; j++) {
            int r = row0 + ty*4 + i, c = col0 + tx*4 + j;
            if (MODE == 0) C[r*ldc + c] = acc[i][j];
            else           Ch[r*ldc + c] = __float2half(acc[i][j]);
        }
}

// ---------------- weight precompute, stage A --------------------------------
__global__ void precompA2(const float* __restrict__ Wqkv, const float* __restrict__ bqkv,
                          const float* __restrict__ Wq, const float* __restrict__ Wo,
                          const float* __restrict__ Wout)
{
    int blk = blockIdx.x;
    if (blk < 32) {
        int h = blk >> 2, q = blk & 3;
        mm64<0>(Wqkv + h*128, 3*HEADS*DIM, Wq, DIM, 0,
                g_Wf + h*DIM*DIM, 0, DIM, (q>>1)*64, (q&1)*64);
    } else if (blk < 64) {
        int h = (blk-32) >> 2, q = (blk-32) & 3;
        mm64<0>(Wo, DIM, Wout + h*DIM*DIM, DIM, 0,
                g_T + h*DIM*DIM, 0, DIM, (q>>1)*64, (q&1)*64);
    } else {
        for (int o = threadIdx.x; o < HEADS*DIM; o += 256) {
            int h = o >> 7, e = o & 127;
            float s = 0.f;
#pragma unroll 8
            for (int c = 0; c < 128; c++) s += bqkv[h*128+c] * Wq[c*128+e];
            g_bf[o] = s;
        }
    }
}

// ---------------- weight precompute, stage B --------------------------------
__global__ void precompB2(const float* __restrict__ Wk, const float* __restrict__ Wv,
                          const float* __restrict__ Wout, const float* __restrict__ bo,
                          const float* __restrict__ bout)
{
    int blk = blockIdx.x;
    if (blk < 32) {
        int h = blk >> 2, q = blk & 3;
        // M_h = Wf_h @ Wk^T -> fp16 at [row][h*128+col] (ldc 1024)
        mm64<1>(g_Wf + h*DIM*DIM, DIM, Wk, DIM, 1, 0,
                g_Mh + h*DIM, HEADS*DIM, (q>>1)*64, (q&1)*64);
    } else if (blk < 64) {
        int h = (blk-32) >> 2, q = (blk-32) & 3;
        // W3_h = Wv @ T_h -> fp16 rows h*128.. of [1024][128]
        mm64<1>(Wv, DIM, g_T + h*DIM*DIM, DIM, 0, 0,
                g_W3h + h*DIM*DIM, DIM, (q>>1)*64, (q&1)*64);
    } else if (blk == 64) {
        for (int o = threadIdx.x; o < HEADS*DIM; o += 256) {
            int h = o >> 7, d2 = o & 127;
            float s = 0.f;
#pragma unroll 8
            for (int e = 0; e < 128; e++) s += g_bf[h*128+e] * Wk[d2*128+e];
            g_bu[o] = s;
        }
    } else {
        __shared__ float part[256];
        int e = threadIdx.x & 127, half = threadIdx.x >> 7;
        float s = 0.f;
#pragma unroll 8
        for (int c = half*512; c < half*512 + 512; c++) s += bo[c & 127] * Wout[c*128 + e];
        part[threadIdx.x] = s;
        __syncthreads();
        if (half == 0) g_bfinal[e] = part[e] + part[128+e] + bout[e];
    }
}

// ---------------- layernorm: warp per row, float4 ---------------------------
__global__ void ln_kernel(const float* __restrict__ x, const float* __restrict__ g,
                          const float* __restrict__ b)
{
    int wid = threadIdx.x >> 5, lane = threadIdx.x & 31;
    int row = blockIdx.x * 8 + wid;
    float4 v = ((const float4*)x)[row*32 + lane];
    float s = v.x + v.y + v.z + v.w;
    float s2 = v.x*v.x + v.y*v.y + v.z*v.z + v.w*v.w;
#pragma unroll
    for (int o = 16; o > 0; o >>= 1) {
        s  += __shfl_xor_sync(0xffffffffu, s, o);
        s2 += __shfl_xor_sync(0xffffffffu, s2, o);
    }
    float mu = s * (1.f/128.f);
    float var = s2 * (1.f/128.f) - mu*mu;
    float inv = rsqrtf(var + 1e-5f);
    float4 g4 = ((const float4*)g)[lane];
    float4 b4 = ((const float4*)b)[lane];
    float4 xn;
    xn.x = (v.x - mu)*inv*g4.x + b4.x;
    xn.y = (v.y - mu)*inv*g4.y + b4.y;
    xn.z = (v.z - mu)*inv*g4.z + b4.z;
    xn.w = (v.w - mu)*inv*g4.w + b4.w;
    ((float4*)g_xn)[row*32 + lane] = xn;
    __half2 lo2 = __floats2half2_rn(xn.x, xn.y);
    __half2 hi2 = __floats2half2_rn(xn.z, xn.w);
    *(__half2*)&g_XNh[row*DIM + lane*4]     = lo2;
    *(__half2*)&g_XNh[row*DIM + lane*4 + 2] = hi2;
}

// ---------------- integral image: batched-load register scans ---------------
__global__ void rowcum_kernel()
{
    int bh = blockIdx.x;
    int d = threadIdx.x;
    float v[GRID];
#pragma unroll
    for (int w = 0; w < GRID; w++) v[w] = g_xn[(bh*GRID + w)*DIM + d];
    float run = 0.f;
#pragma unroll
    for (int w = 0; w < GRID; w++) {
        run += v[w];
        g_S[(bh*GRID + w)*DIM + d] = run;
    }
}

__global__ void colcum_kernel()
{
    int b = blockIdx.x >> 5, w = blockIdx.x & 31;
    int d = threadIdx.x;
    float v[GRID];
#pragma unroll
    for (int h = 0; h < GRID; h++) v[h] = g_S[((b*GRID + h)*GRID + w)*DIM + d];
    float run = 0.f;
#pragma unroll
    for (int h = 0; h < GRID; h++) {
        run += v[h];
        g_S[((b*GRID + h)*GRID + w)*DIM + d] = run;
    }
}

// ---------------- region means ----------------------------------------------
__global__ void regions_kernel()
{
    int pos = blockIdx.x;
    int b = pos >> 10;
    int hw = pos & 1023;
    int h = hw >> 5, w = hw & 31;
    int d = threadIdx.x;
    const float* Sb = g_S + b*GRID*GRID*DIM;
#define SS(hh,ww) (((hh) < 0 || (ww) < 0) ? 0.f : Sb[((hh)*GRID + (ww))*DIM + d])
    float s_hw  = SS(h, w);
    float s_hW  = SS(h, GRID-1);
    float s_Hw  = SS(GRID-1, w);
    float s_HW  = SS(GRID-1, GRID-1);
    float s_h1w1 = SS(h-1, w-1);
    float s_h1w  = SS(h-1, w);
    float s_hw1  = SS(h, w-1);
    float s_h1W  = SS(h-1, GRID-1);
    float s_Hw1  = SS(GRID-1, w-1);
#undef SS
    float hp1 = (float)(h+1), wp1 = (float)(w+1);
    float hr = (float)(GRID - h), wr = (float)(GRID - w);
    float* R = g_regions + pos*4*DIM;
    R[0*DIM + d] = s_hw / (hp1*wp1);
    R[1*DIM + d] = (s_hW - s_hw1) / (hp1*wr);
    R[2*DIM + d] = (s_Hw - s_h1w) / (hr*wp1);
    R[3*DIM + d] = (s_HW - s_h1W - s_Hw1 + s_h1w1) / (hr*wr);
}

// ---------------- fused: U-GEMM (fp16, K=128) + softmax + aggregate ---------
__global__ __launch_bounds__(256) void gemmU_fused()
{
    extern __shared__ char sbuf[];
    __half* As = (__half*)sbuf;                  // 2 x 128x72
    __half* Bs = (__half*)(sbuf + 36864);        // 2 x 64x136
    float* Uf = (float*)sbuf;                    // 128x132 (aliases A/B)

    const int tid = threadIdx.x;
    const int wid = tid >> 5, lane = tid & 31;
    const int wm = wid & 1, wn = wid >> 1;       // warp tile 64x32
    const int m0 = blockIdx.x * 128;
    const int h  = blockIdx.y;
    const int n0 = h * 128;

    float acc[4][4][4];
#pragma unroll
    for (int mt = 0; mt < 4; mt++)
#pragma unroll
        for (int nt = 0; nt < 4; nt++)
#pragma unroll
            for (int q = 0; q < 4; q++) acc[mt][nt][q] = 0.f;

    auto LOAD = [&](int s, int buf) {
        int k0 = s * 64;
#pragma unroll
        for (int i = 0; i < 4; i++) {
            int c = tid + i*256;
            int row = c >> 3, col8 = (c & 7) * 8;
            cp_async16(As + buf*9216 + row*72 + col8,
                       g_XNh + (m0+row)*DIM + k0 + col8);
        }
#pragma unroll
        for (int i = 0; i < 4; i++) {
            int c = tid + i*256;
            int kr = c >> 4, col8 = (c & 15) * 8;
            cp_async16(Bs + buf*8704 + kr*136 + col8,
                       g_Mh + (k0+kr)*(HEADS*DIM) + n0 + col8);
        }
        asm volatile("cp.async.commit_group;");
    };

    const unsigned as_base = smem_u32(As), bs_base = smem_u32(Bs);
    unsigned a_off[4], b_off[4];
#pragma unroll
    for (int mt = 0; mt < 4; mt++)
        a_off[mt] = ((wm*64 + mt*16 + (lane & 15))*72 + (lane >> 4)*8)*2;
#pragma unroll
    for (int nt = 0; nt < 4; nt++)
        b_off[nt] = ((lane & 15)*136 + wn*32 + nt*8)*2;

    auto COMPUTE = [&](int buf) {
#pragma unroll
        for (int kk = 0; kk < 4; kk++) {
            unsigned af[4][4];
#pragma unroll
            for (int mt = 0; mt < 4; mt++)
                ldmatrix_x4(af[mt], as_base + buf*18432 + a_off[mt] + kk*32);
#pragma unroll
            for (int nt = 0; nt < 4; nt++) {
                unsigned bfr[2];
                ldmatrix_x2t(bfr, bs_base + buf*17408 + b_off[nt] + kk*4352);
#pragma unroll
                for (int mt = 0; mt < 4; mt++) mma_f16(acc[mt][nt], af[mt], bfr);
            }
        }
    };

    LOAD(0, 0);
    LOAD(1, 1);
    asm volatile("cp.async.wait_group 1;");
    __syncthreads();
    COMPUTE(0);
    __syncthreads();
    asm volatile("cp.async.wait_group 0;");
    __syncthreads();
    COMPUTE(1);
    __syncthreads();

    // ---- write U tile (acc + bias) into smem fp32 -------------------------
    const int tr = lane >> 2, tc = (lane & 3)*2;
    const int r0 = wm*64, c0 = wn*32;
#pragma unroll
    for (int mt = 0; mt < 4; mt++)
#pragma unroll
        for (int nt = 0; nt < 4; nt++) {
            int row = r0 + mt*16 + tr, col = c0 + nt*8 + tc;
            float b0 = g_bu[n0 + col], b1 = g_bu[n0 + col + 1];
            *(float2*)&Uf[row*132 + col] =
                make_float2(acc[mt][nt][0] + b0, acc[mt][nt][1] + b1);
            *(float2*)&Uf[(row+8)*132 + col] =
                make_float2(acc[mt][nt][2] + b0, acc[mt][nt][3] + b1);
        }
    __syncthreads();

    // ---- per-warp: scores, softmax, aggregate, write C fp16 ---------------
    for (int i = 0; i < 16; i++) {
        int p = wid*16 + i;
        int gpos = m0 + p;
        const float* Rp = g_regions + (size_t)gpos*4*DIM;
        float s0 = 0.f, s1 = 0.f, s2 = 0.f, s3 = 0.f;
#pragma unroll
        for (int c2 = 0; c2 < 4; c2++) {
            int d = lane + c2*32;
            float u = Uf[p*132 + d];
            s0 += u * Rp[d];
            s1 += u * Rp[DIM + d];
            s2 += u * Rp[2*DIM + d];
            s3 += u * Rp[3*DIM + d];
        }
#pragma unroll
        for (int o = 16; o > 0; o >>= 1) {
            s0 += __shfl_xor_sync(0xffffffffu, s0, o);
            s1 += __shfl_xor_sync(0xffffffffu, s1, o);
            s2 += __shfl_xor_sync(0xffffffffu, s2, o);
            s3 += __shfl_xor_sync(0xffffffffu, s3, o);
        }
        s0 *= 0.25f; s1 *= 0.25f; s2 *= 0.25f; s3 *= 0.25f;
        float m = fmaxf(fmaxf(s0, s1), fmaxf(s2, s3));
        float e0 = expf(s0 - m), e1 = expf(s1 - m), e2 = expf(s2 - m), e3 = expf(s3 - m);
        float inv = 1.f / (e0 + e1 + e2 + e3);
        float p0 = e0*inv, p1 = e1*inv, p2 = e2*inv, p3 = e3*inv;
#pragma unroll
        for (int c2 = 0; c2 < 4; c2++) {
            int d = lane + c2*32;
            float cv = p0*Rp[d] + p1*Rp[DIM + d] + p2*Rp[2*DIM + d] + p3*Rp[3*DIM + d];
            g_Ch[(size_t)gpos*(HEADS*DIM) + n0 + d] = __float2half(cv);
        }
    }
}

// ---------------- Y = C @ W3cat + bfinal  ->  out directly ------------------
// [8192,1024] x [1024,128]; block = 64 rows, K double-buffered in 16 stages.
__global__ __launch_bounds__(256) void gemmY3(float* __restrict__ out)
{
    extern __shared__ char sbuf[];
    __half* As = (__half*)sbuf;                  // 2 x 64x72
    __half* Bs = (__half*)(sbuf + 18432);        // 2 x 64x136

    const int tid = threadIdx.x;
    const int wid = tid >> 5, lane = tid & 31;
    const int wm = wid & 1, wn = wid >> 1;       // warp tile 32x32
    const int m0 = blockIdx.x * 64;

    float acc[2][4][4];
#pragma unroll
    for (int mt = 0; mt < 2; mt++)
#pragma unroll
        for (int nt = 0; nt < 4; nt++)
#pragma unroll
            for (int q = 0; q < 4; q++) acc[mt][nt][q] = 0.f;

    auto LOAD = [&](int s, int buf) {
        int k0 = s * 64;
#pragma unroll
        for (int i = 0; i < 2; i++) {
            int c = tid + i*256;
            int row = c >> 3, col8 = (c & 7) * 8;
            cp_async16(As + buf*4608 + row*72 + col8,
                       g_Ch + (size_t)(m0+row)*(HEADS*DIM) + k0 + col8);
        }
#pragma unroll
        for (int i = 0; i < 4; i++) {
            int c = tid + i*256;
            int kr = c >> 4, col8 = (c & 15) * 8;
            cp_async16(Bs + buf*8704 + kr*136 + col8,
                       g_W3h + (k0+kr)*DIM + col8);
        }
        asm volatile("cp.async.commit_group;");
    };

    const unsigned as_base = smem_u32(As), bs_base = smem_u32(Bs);
    unsigned a_off[2], b_off[4];
#pragma unroll
    for (int mt = 0; mt < 2; mt++)
        a_off[mt] = ((wm*32 + mt*16 + (lane & 15))*72 + (lane >> 4)*8)*2;
#pragma unroll
    for (int nt = 0; nt < 4; nt++)
        b_off[nt] = ((lane & 15)*136 + wn*32 + nt*8)*2;

    auto COMPUTE = [&](int buf) {
#pragma unroll
        for (int kk = 0; kk < 4; kk++) {
            unsigned af[2][4];
#pragma unroll
            for (int mt = 0; mt < 2; mt++)
                ldmatrix_x4(af[mt], as_base + buf*9216 + a_off[mt] + kk*32);
#pragma unroll
            for (int nt = 0; nt < 4; nt++) {
                unsigned bfr[2];
                ldmatrix_x2t(bfr, bs_base + buf*17408 + b_off[nt] + kk*4352);
#pragma unroll
                for (int mt = 0; mt < 2; mt++) mma_f16(acc[mt][nt], af[mt], bfr);
            }
        }
    };

    LOAD(0, 0);
    for (int s = 0; s < 16; s++) {
        int cur = s & 1;
        if (s < 15) {
            LOAD(s+1, cur^1);
            asm volatile("cp.async.wait_group 1;");
        } else {
            asm volatile("cp.async.wait_group 0;");
        }
        __syncthreads();
        COMPUTE(cur);
        __syncthreads();
    }

    const int tr = lane >> 2, tc = (lane & 3)*2;
#pragma unroll
    for (int mt = 0; mt < 2; mt++)
#pragma unroll
        for (int nt = 0; nt < 4; nt++) {
            int row = m0 + wm*32 + mt*16 + tr, col = wn*32 + nt*8 + tc;
            float b0 = g_bfinal[col], b1 = g_bfinal[col+1];
            *(float2*)&out[(size_t)row*DIM + col] =
                make_float2(acc[mt][nt][0] + b0, acc[mt][nt][1] + b1);
            *(float2*)&out[(size_t)(row+8)*DIM + col] =
                make_float2(acc[mt][nt][2] + b0, acc[mt][nt][3] + b1);
        }
}

// ---------------- launch -----------------------------------------------------
extern "C" void kernel_launch(void* const* d_in, const int* in_sizes, int n_in,
                              void* d_out, int out_size)
{
    const float* x    = (const float*)d_in[0];
    const float* ln_g = (const float*)d_in[1];
    const float* ln_b = (const float*)d_in[2];
    const float* Wqkv = (const float*)d_in[3];
    const float* bqkv = (const float*)d_in[4];
    const float* Wq   = (const float*)d_in[5];
    const float* Wk   = (const float*)d_in[6];
    const float* Wv   = (const float*)d_in[7];
    const float* Wo   = (const float*)d_in[8];
    const float* bo   = (const float*)d_in[9];
    const float* Wout = (const float*)d_in[10];
    const float* bout = (const float*)d_in[11];
    float* out = (float*)d_out;

    cudaFuncSetAttribute(gemmU_fused, cudaFuncAttributeMaxDynamicSharedMemorySize, GEMM_SMEM);
    cudaFuncSetAttribute(gemmY3,      cudaFuncAttributeMaxDynamicSharedMemorySize, GEMMY_SMEM);

    precompA2<<<65, 256>>>(Wqkv, bqkv, Wq, Wo, Wout);
    precompB2<<<66, 256>>>(Wk, Wv, Wout, bo, bout);
    ln_kernel<<<POSITIONS/8, 256>>>(x, ln_g, ln_b);
    rowcum_kernel<<<BATCH*GRID, 128>>>();
    colcum_kernel<<<BATCH*GRID, 128>>>();
    regions_kernel<<<POSITIONS, 128>>>();
    gemmU_fused<<<dim3(POSITIONS/128, HEADS), 256, GEMM_SMEM>>>();
    gemmY3<<<POSITIONS/64, 256, GEMMY_SMEM>>>(out);
}